// round 11
// baseline (speedup 1.0000x reference)
#include <cuda_runtime.h>
#include <cstdint>

#define E 1024
#define R 16
#define BATCH 4
#define S 2048
#define BS (BATCH * S)

// ---------------- device scratch ----------------
__device__ float g_Weff[3][(size_t)E * E];                 // 12 MB
__device__ float g_QKV[3][(size_t)BATCH * S * E];          // 96 MB
__device__ float g_Vt[(size_t)BATCH * S * E];              // 32 MB (V^T per batch: [E][S])
__device__ float g_scores[(size_t)BATCH * S * S];          // 64 MB
__device__ float g_attnout[(size_t)BATCH * S * E];         // 32 MB

#define SEL_EXT   0
#define SEL_WEFF  1
#define SEL_QKV   2
#define SEL_SCORE 3
#define SEL_AOUT  4
#define SEL_VT    5

__device__ __forceinline__ float* resolve_buf(int sel, const float* ext) {
    switch (sel) {
        case SEL_WEFF:  return &g_Weff[0][0];
        case SEL_QKV:   return &g_QKV[0][0];
        case SEL_SCORE: return &g_scores[0];
        case SEL_AOUT:  return &g_attnout[0];
        case SEL_VT:    return &g_Vt[0];
        default:        return (float*)ext;
    }
}

// ---------------- bf16 helpers ----------------
__device__ __forceinline__ uint32_t bf16x2_rn(float x0, float x1) {
    uint32_t r;
    asm("cvt.rn.bf16x2.f32 %0, %1, %2;" : "=r"(r) : "f"(x1), "f"(x0));
    return r;
}
__device__ __forceinline__ float bf_lo_f(uint32_t w) { return __uint_as_float(w << 16); }
__device__ __forceinline__ float bf_hi_f(uint32_t w) { return __uint_as_float(w & 0xffff0000u); }

__device__ __forceinline__ void mma_bf16(float* c, const uint32_t* a, const uint32_t* b) {
    asm volatile("mma.sync.aligned.m16n8k16.row.col.f32.bf16.bf16.f32 "
        "{%0,%1,%2,%3}, {%4,%5,%6,%7}, {%8,%9}, {%0,%1,%2,%3};"
        : "+f"(c[0]), "+f"(c[1]), "+f"(c[2]), "+f"(c[3])
        : "r"(a[0]), "r"(a[1]), "r"(a[2]), "r"(a[3]), "r"(b[0]), "r"(b[1]));
}

// ---------------- W_eff = W + B @ A ----------------
__global__ __launch_bounds__(256) void weff_kernel(
    const float* __restrict__ Wq, const float* __restrict__ Wk, const float* __restrict__ Wv,
    const float* __restrict__ Aq, const float* __restrict__ Bq,
    const float* __restrict__ Ak, const float* __restrict__ Bk,
    const float* __restrict__ Av, const float* __restrict__ Bv)
{
    const int z = blockIdx.z;
    const float* W  = (z == 0) ? Wq : (z == 1) ? Wk : Wv;
    const float* Am = (z == 0) ? Aq : (z == 1) ? Ak : Av;
    const float* Bm = (z == 0) ? Bq : (z == 1) ? Bk : Bv;
    const int idx = blockIdx.x * 256 + threadIdx.x;
    const int f = idx >> 10;
    const int e = idx & 1023;
    float sum = W[idx];
#pragma unroll
    for (int r = 0; r < R; r++)
        sum += Bm[f * R + r] * Am[r * E + e];
    g_Weff[z][idx] = sum;
}

// ---------------- V transpose: Vt[b][e][s] = V[b][s][e] ----------------
__global__ __launch_bounds__(256) void transpose_v_kernel()
{
    __shared__ float t[32][33];
    const int b = blockIdx.z;
    const int s0 = blockIdx.x * 32;
    const int e0 = blockIdx.y * 32;
    const int tx = threadIdx.x & 31;
    const int ty = threadIdx.x >> 5;   // 0..7
    const float* V = &g_QKV[2][0] + (long long)b * S * E;
    float* Vt = &g_Vt[0] + (long long)b * S * E;
#pragma unroll
    for (int r = 0; r < 4; r++)
        t[ty + r * 8][tx] = V[(long long)(s0 + ty + r * 8) * E + e0 + tx];
    __syncthreads();
#pragma unroll
    for (int r = 0; r < 4; r++)
        Vt[(long long)(e0 + ty + r * 8) * S + s0 + tx] = t[tx][ty + r * 8];
}

// ---------------- split-BF16 3-term HMMA GEMM, warp-specialized ----------------
// C[M,N] = alpha * A[M,K] @ B[N,K]^T (row-major). x -> bf16 hi + bf16 lo;
// acc += Ah*Bh + Al*Bh + Ah*Bl (Al*Bl dropped, ~2^-16 rel; fp32 TC accum).
// CTA 128x128x32, 384 threads: warps 0-7 COMPUTE (2x4, 64x32 warp tiles),
// warps 8-11 PRODUCE (LDG -> split/cvt -> STS for step+1) — producer work
// overlaps compute across warps instead of interleaving within warps.
// Double-buffered; one uniform __syncthreads per step.
// Smem word layout per buffer (8192 words): identical to R9 (proven):
//  A hi 0..2047, A lo 2048..4095   (fb = (m>>4)*2 + kc, 128-word frag blocks)
//  B hi 4096..6143, B lo 6144..8191 (fb = (n>>3)*2 + kc, 64-word frag blocks)
#define GEMM_SMEM_BYTES (2 * 8192 * 4)
#define GEMM_THREADS 384

__global__ __launch_bounds__(GEMM_THREADS, 1) void gemm_hmma(
    const float* extA0, const float* extA1, const float* extA2,
    int selA, long long offA, int ldA, long long sA,
    const float* extB, int selB, long long offB, int ldB, long long sB,
    float* extC, int selC, long long offC, int ldC, long long sC,
    int K, float alpha)
{
    extern __shared__ uint32_t smw[];
    const int tid = threadIdx.x;
    const int wid = tid >> 5, lane = tid & 31;
    const int g = lane >> 2, t4 = lane & 3;
    const bool is_producer = (wid >= 8);
    const int warp_m = wid & 1, warp_n = (wid >> 1) & 3;  // compute warps 0-7

    const float* extAz = (blockIdx.z == 0) ? extA0 : (blockIdx.z == 1) ? extA1 : extA2;
    const float* Ag = resolve_buf(selA, extAz) + offA + (long long)blockIdx.z * sA
                      + (long long)blockIdx.y * 128 * ldA;
    const float* Bg = resolve_buf(selB, extB) + offB + (long long)blockIdx.z * sB
                      + (long long)blockIdx.x * 128 * ldB;
    float* Cg = resolve_buf(selC, extC) + offC + (long long)blockIdx.z * sC;

    float acc[4][4][4];
#pragma unroll
    for (int i = 0; i < 4; i++)
#pragma unroll
        for (int j = 0; j < 4; j++)
#pragma unroll
            for (int q = 0; q < 4; q++) acc[i][j][q] = 0.f;

    // ---- producer: 128 threads (ptid 0..127) cover 1024 A + 1024 B float4 slots
    const int ptid = tid - 256;
    auto produce = [&](int step, int s) {
        uint32_t* base = smw + s * 8192;
#pragma unroll
        for (int h = 0; h < 2; h++) {
            float4 va[4], vb[4];
#pragma unroll
            for (int j = 0; j < 4; j++) {
                const int i = ptid + (h * 4 + j) * 128;   // 0..1023
                const int m = i >> 3, q = i & 7;
                va[j] = *reinterpret_cast<const float4*>(Ag + (long long)m * ldA + step * 32 + q * 4);
                vb[j] = *reinterpret_cast<const float4*>(Bg + (long long)m * ldB + step * 32 + q * 4);
            }
#pragma unroll
            for (int j = 0; j < 4; j++) {
                const int i = ptid + (h * 4 + j) * 128;
                const int m = i >> 3, q = i & 7;
                const int kc = q >> 2;
                const int khalf = (q >> 1) & 1;
                const int tp = (q & 1) * 2;
                const float xs[4] = { va[j].x, va[j].y, va[j].z, va[j].w };
                const float ys[4] = { vb[j].x, vb[j].y, vb[j].z, vb[j].w };
                // A
                {
                    const int fb = (m >> 4) * 2 + kc;
                    const int reg = ((m >> 3) & 1) + 2 * khalf;
#pragma unroll
                    for (int w = 0; w < 2; w++) {
                        const float x0 = xs[w * 2], x1 = xs[w * 2 + 1];
                        const uint32_t hh = bf16x2_rn(x0, x1);
                        const uint32_t ll = bf16x2_rn(x0 - bf_lo_f(hh), x1 - bf_hi_f(hh));
                        const int idx = fb * 128 + ((m & 7) * 4 + tp + w) * 4 + reg;
                        base[idx] = hh;
                        base[2048 + idx] = ll;
                    }
                }
                // B (row n = m)
                {
                    const int fb = (m >> 3) * 2 + kc;
#pragma unroll
                    for (int w = 0; w < 2; w++) {
                        const float x0 = ys[w * 2], x1 = ys[w * 2 + 1];
                        const uint32_t hh = bf16x2_rn(x0, x1);
                        const uint32_t ll = bf16x2_rn(x0 - bf_lo_f(hh), x1 - bf_hi_f(hh));
                        const int idx = fb * 64 + ((m & 7) * 4 + tp + w) * 2 + khalf;
                        base[4096 + idx] = hh;
                        base[6144 + idx] = ll;
                    }
                }
            }
        }
    };

    // ---- consumer: one kc (k16) block; bF streamed in nt-pairs (regs capped)
    auto compute_kc = [&](int s, int kc) {
        const uint32_t* base = smw + s * 8192;
        uint32_t aF[2][4][4];
#pragma unroll
        for (int mt = 0; mt < 4; mt++) {
            const int fb = (warp_m * 4 + mt) * 2 + kc;
            const uint4 h = *reinterpret_cast<const uint4*>(base + fb * 128 + lane * 4);
            const uint4 l = *reinterpret_cast<const uint4*>(base + 2048 + fb * 128 + lane * 4);
            aF[0][mt][0] = h.x; aF[0][mt][1] = h.y; aF[0][mt][2] = h.z; aF[0][mt][3] = h.w;
            aF[1][mt][0] = l.x; aF[1][mt][1] = l.y; aF[1][mt][2] = l.z; aF[1][mt][3] = l.w;
        }
#pragma unroll
        for (int nh = 0; nh < 2; nh++) {
            uint32_t bF[2][2][2];
#pragma unroll
            for (int nt = 0; nt < 2; nt++) {
                const int fb = (warp_n * 4 + nh * 2 + nt) * 2 + kc;
                const uint2 h = *reinterpret_cast<const uint2*>(base + 4096 + fb * 64 + lane * 2);
                const uint2 l = *reinterpret_cast<const uint2*>(base + 6144 + fb * 64 + lane * 2);
                bF[0][nt][0] = h.x; bF[0][nt][1] = h.y;
                bF[1][nt][0] = l.x; bF[1][nt][1] = l.y;
            }
            // term 1: Ah * Bh
#pragma unroll
            for (int mt = 0; mt < 4; mt++)
#pragma unroll
                for (int nt = 0; nt < 2; nt++)
                    mma_bf16(acc[mt][nh * 2 + nt], aF[0][mt], bF[0][nt]);
            // term 2: Al * Bh
#pragma unroll
            for (int mt = 0; mt < 4; mt++)
#pragma unroll
                for (int nt = 0; nt < 2; nt++)
                    mma_bf16(acc[mt][nh * 2 + nt], aF[1][mt], bF[0][nt]);
            // term 3: Ah * Bl   (Al*Bl dropped)
#pragma unroll
            for (int mt = 0; mt < 4; mt++)
#pragma unroll
                for (int nt = 0; nt < 2; nt++)
                    mma_bf16(acc[mt][nh * 2 + nt], aF[0][mt], bF[1][nt]);
        }
    };

    const int nsteps = K / 32;
    if (is_producer) produce(0, 0);
    __syncthreads();

    for (int step = 0; step < nsteps; step++) {
        const int s = step & 1;
        if (is_producer) {
            if (step + 1 < nsteps) produce(step + 1, 1 - s);
        } else {
            compute_kc(s, 0);
            compute_kc(s, 1);
        }
        __syncthreads();
    }

    // ---- epilogue (compute warps only): rows warp_m*64..+63, cols warp_n*32..+31
    if (!is_producer) {
#pragma unroll
        for (int mt = 0; mt < 4; mt++) {
            const long long row = (long long)blockIdx.y * 128 + warp_m * 64 + mt * 16 + g;
            const long long col0 = (long long)blockIdx.x * 128 + warp_n * 32;
#pragma unroll
            for (int nt = 0; nt < 4; nt++) {
                const long long col = col0 + nt * 8 + t4 * 2;
                float2 v0 = make_float2(acc[mt][nt][0] * alpha, acc[mt][nt][1] * alpha);
                float2 v1 = make_float2(acc[mt][nt][2] * alpha, acc[mt][nt][3] * alpha);
                *reinterpret_cast<float2*>(Cg + row * ldC + col) = v0;
                *reinterpret_cast<float2*>(Cg + (row + 8) * ldC + col) = v1;
            }
        }
    }
}

// ---------------- row softmax over S=2048 ----------------
__global__ __launch_bounds__(256) void softmax_kernel()
{
    const long long row = blockIdx.x;
    float* p = &g_scores[0] + row * (long long)S;
    const int t = threadIdx.x;

    float v[8];
    float m = -1e30f;
#pragma unroll
    for (int i = 0; i < 8; i++) {
        v[i] = p[t + i * 256];
        m = fmaxf(m, v[i]);
    }
    __shared__ float red[8];
#pragma unroll
    for (int o = 16; o; o >>= 1) m = fmaxf(m, __shfl_xor_sync(0xffffffffu, m, o));
    if ((t & 31) == 0) red[t >> 5] = m;
    __syncthreads();
    float mx = red[0];
#pragma unroll
    for (int w = 1; w < 8; w++) mx = fmaxf(mx, red[w]);

    float s = 0.f;
#pragma unroll
    for (int i = 0; i < 8; i++) {
        v[i] = __expf(v[i] - mx);
        s += v[i];
    }
#pragma unroll
    for (int o = 16; o; o >>= 1) s += __shfl_xor_sync(0xffffffffu, s, o);
    __syncthreads();
    if ((t & 31) == 0) red[t >> 5] = s;
    __syncthreads();
    float tot = 0.f;
#pragma unroll
    for (int w = 0; w < 8; w++) tot += red[w];
    const float inv = 1.0f / tot;
#pragma unroll
    for (int i = 0; i < 8; i++) p[t + i * 256] = v[i] * inv;
}

// ---------------- launch ----------------
extern "C" void kernel_launch(void* const* d_in, const int* in_sizes, int n_in,
                              void* d_out, int out_size)
{
    (void)in_sizes; (void)n_in; (void)out_size;
    const float* query = (const float*)d_in[0];
    const float* key   = (const float*)d_in[1];
    const float* value = (const float*)d_in[2];
    const float* Qw    = (const float*)d_in[3];
    const float* Kw    = (const float*)d_in[4];
    const float* Vw    = (const float*)d_in[5];
    const float* Qa    = (const float*)d_in[6];
    const float* Qb    = (const float*)d_in[7];
    const float* Ka    = (const float*)d_in[8];
    const float* Kb    = (const float*)d_in[9];
    const float* Va    = (const float*)d_in[10];
    const float* Vb    = (const float*)d_in[11];
    const float* Ow    = (const float*)d_in[12];
    float* out = (float*)d_out;

    static bool attr_done = false;
    if (!attr_done) {
        cudaFuncSetAttribute(gemm_hmma, cudaFuncAttributeMaxDynamicSharedMemorySize,
                             GEMM_SMEM_BYTES);
        attr_done = true;
    }

    const long long EE  = (long long)E * E;
    const long long BSE = (long long)BATCH * S * E;
    const long long SE  = (long long)S * E;
    const long long SS  = (long long)S * S;

    // 1. fold LoRA into weights
    weff_kernel<<<dim3(E * E / 256, 1, 3), 256>>>(Qw, Kw, Vw, Qa, Qb, Ka, Kb, Va, Vb);

    // 2. Q/K/V projections merged into ONE launch: z picks input + weight/output offset
    gemm_hmma<<<dim3(E / 128, BS / 128, 3), GEMM_THREADS, GEMM_SMEM_BYTES>>>(
        query, key, value, SEL_EXT, 0, E, 0,
        nullptr, SEL_WEFF, 0, E, EE,
        nullptr, SEL_QKV,  0, E, BSE,
        E, 1.0f);

    // 3. transpose V -> Vt[b][e][s]
    transpose_v_kernel<<<dim3(S / 32, E / 32, BATCH), 256>>>();

    // 4. scores = Q @ K^T / 32
    gemm_hmma<<<dim3(S / 128, S / 128, BATCH), GEMM_THREADS, GEMM_SMEM_BYTES>>>(
        nullptr, nullptr, nullptr, SEL_QKV, 0, E, SE,
        nullptr, SEL_QKV,   BSE, E, SE,
        nullptr, SEL_SCORE, 0,   S, SS,
        E, 1.0f / 32.0f);

    // 5. softmax rows
    softmax_kernel<<<BATCH * S, 256>>>();

    // 6. attn_out = P @ Vt^T   (NT with Vt as [E,S] K-major)
    gemm_hmma<<<dim3(E / 128, S / 128, BATCH), GEMM_THREADS, GEMM_SMEM_BYTES>>>(
        nullptr, nullptr, nullptr, SEL_SCORE, 0, S, SS,
        nullptr, SEL_VT,   0, S, SE,
        nullptr, SEL_AOUT, 0, E, SE,
        S, 1.0f);

    // 7. final = attn_out @ O^T
    gemm_hmma<<<dim3(E / 128, BS / 128, 1), GEMM_THREADS, GEMM_SMEM_BYTES>>>(
        nullptr, nullptr, nullptr, SEL_AOUT, 0, E, 0,
        Ow,  SEL_EXT, 0, E, 0,
        out, SEL_EXT, 0, E, 0,
        E, 1.0f);
}

// round 12
// speedup vs baseline: 1.2540x; 1.2540x over previous
#include <cuda_runtime.h>
#include <cstdint>

#define E 1024
#define R 16
#define BATCH 4
#define S 2048
#define BS (BATCH * S)

// ---------------- device scratch ----------------
__device__ float g_Weff[3][(size_t)E * E];                 // 12 MB
__device__ float g_QKV[3][(size_t)BATCH * S * E];          // 96 MB
__device__ float g_Vt[(size_t)BATCH * S * E];              // 32 MB (V^T per batch: [E][S])
__device__ float g_scores[(size_t)BATCH * S * S];          // 64 MB
__device__ float g_attnout[(size_t)BATCH * S * E];         // 32 MB

#define SEL_EXT   0
#define SEL_WEFF  1
#define SEL_QKV   2
#define SEL_SCORE 3
#define SEL_AOUT  4
#define SEL_VT    5

__device__ __forceinline__ float* resolve_buf(int sel, const float* ext) {
    switch (sel) {
        case SEL_WEFF:  return &g_Weff[0][0];
        case SEL_QKV:   return &g_QKV[0][0];
        case SEL_SCORE: return &g_scores[0];
        case SEL_AOUT:  return &g_attnout[0];
        case SEL_VT:    return &g_Vt[0];
        default:        return (float*)ext;
    }
}

// ---------------- bf16 helpers ----------------
__device__ __forceinline__ uint32_t bf16x2_rn(float x0, float x1) {
    uint32_t r;
    asm("cvt.rn.bf16x2.f32 %0, %1, %2;" : "=r"(r) : "f"(x1), "f"(x0));
    return r;
}
__device__ __forceinline__ float bf_lo_f(uint32_t w) { return __uint_as_float(w << 16); }
__device__ __forceinline__ float bf_hi_f(uint32_t w) { return __uint_as_float(w & 0xffff0000u); }

__device__ __forceinline__ void mma_bf16(float* c, const uint32_t* a, const uint32_t* b) {
    asm volatile("mma.sync.aligned.m16n8k16.row.col.f32.bf16.bf16.f32 "
        "{%0,%1,%2,%3}, {%4,%5,%6,%7}, {%8,%9}, {%0,%1,%2,%3};"
        : "+f"(c[0]), "+f"(c[1]), "+f"(c[2]), "+f"(c[3])
        : "r"(a[0]), "r"(a[1]), "r"(a[2]), "r"(a[3]), "r"(b[0]), "r"(b[1]));
}

// ---------------- W_eff = W + B @ A ----------------
__global__ __launch_bounds__(256) void weff_kernel(
    const float* __restrict__ Wq, const float* __restrict__ Wk, const float* __restrict__ Wv,
    const float* __restrict__ Aq, const float* __restrict__ Bq,
    const float* __restrict__ Ak, const float* __restrict__ Bk,
    const float* __restrict__ Av, const float* __restrict__ Bv)
{
    const int z = blockIdx.z;
    const float* W  = (z == 0) ? Wq : (z == 1) ? Wk : Wv;
    const float* Am = (z == 0) ? Aq : (z == 1) ? Ak : Av;
    const float* Bm = (z == 0) ? Bq : (z == 1) ? Bk : Bv;
    const int idx = blockIdx.x * 256 + threadIdx.x;
    const int f = idx >> 10;
    const int e = idx & 1023;
    float sum = W[idx];
#pragma unroll
    for (int r = 0; r < R; r++)
        sum += Bm[f * R + r] * Am[r * E + e];
    g_Weff[z][idx] = sum;
}

// ---------------- V transpose: Vt[b][e][s] = V[b][s][e] ----------------
__global__ __launch_bounds__(256) void transpose_v_kernel()
{
    __shared__ float t[32][33];
    const int b = blockIdx.z;
    const int s0 = blockIdx.x * 32;
    const int e0 = blockIdx.y * 32;
    const int tx = threadIdx.x & 31;
    const int ty = threadIdx.x >> 5;   // 0..7
    const float* V = &g_QKV[2][0] + (long long)b * S * E;
    float* Vt = &g_Vt[0] + (long long)b * S * E;
#pragma unroll
    for (int r = 0; r < 4; r++)
        t[ty + r * 8][tx] = V[(long long)(s0 + ty + r * 8) * E + e0 + tx];
    __syncthreads();
#pragma unroll
    for (int r = 0; r < 4; r++)
        Vt[(long long)(e0 + ty + r * 8) * S + s0 + tx] = t[tx][ty + r * 8];
}

// ---------------- split-BF16 3-term HMMA GEMM, fragment-pipelined ----------------
// C[M,N] = alpha * A[M,K] @ B[N,K]^T (row-major). x -> bf16 hi + bf16 lo;
// acc += Ah*Bh + Al*Bh + Ah*Bl (Al*Bl dropped, ~2^-16 rel; fp32 TC accum).
// CTA 128x128x32, 8 warps (2x4), warp tile 64x32, 1 CTA/SM (regs ~200).
// NEW vs R9: register double-buffering of fragments — aF for kc+1 and bF for
// the next nh block are prefetched from smem WHILE the current MMA block
// issues, hiding the 29-cyc LDS->HMMA dependency that pinned tensor at 50%.
// Producer (LDG/cvt/STS for step+1) interleaved between MMA blocks as in R9.
// Smem word layout per buffer (8192 words), proven since R7:
//  A hi 0..2047, A lo 2048..4095   (fb = (m>>4)*2 + kc, 128-word frag blocks)
//  B hi 4096..6143, B lo 6144..8191 (fb = (n>>3)*2 + kc, 64-word frag blocks)
#define GEMM_SMEM_BYTES (2 * 8192 * 4)
#define NTHREADS 256

__global__ __launch_bounds__(NTHREADS, 1) void gemm_hmma(
    const float* extA0, const float* extA1, const float* extA2,
    int selA, long long offA, int ldA, long long sA,
    const float* extB, int selB, long long offB, int ldB, long long sB,
    float* extC, int selC, long long offC, int ldC, long long sC,
    int K, float alpha)
{
    extern __shared__ uint32_t smw[];
    const int tid = threadIdx.x;
    const int wid = tid >> 5, lane = tid & 31;
    const int g = lane >> 2, t4 = lane & 3;
    const int warp_m = wid & 1, warp_n = wid >> 1;   // 2x4 warps, 64x32 warp tile

    const float* extAz = (blockIdx.z == 0) ? extA0 : (blockIdx.z == 1) ? extA1 : extA2;
    const float* Ag = resolve_buf(selA, extAz) + offA + (long long)blockIdx.z * sA
                      + (long long)blockIdx.y * 128 * ldA;
    const float* Bg = resolve_buf(selB, extB) + offB + (long long)blockIdx.z * sB
                      + (long long)blockIdx.x * 128 * ldB;
    float* Cg = resolve_buf(selC, extC) + offC + (long long)blockIdx.z * sC;

    float acc[4][4][4];
#pragma unroll
    for (int i = 0; i < 4; i++)
#pragma unroll
        for (int j = 0; j < 4; j++)
#pragma unroll
            for (int q = 0; q < 4; q++) acc[i][j][q] = 0.f;

    float4 va[2], vb[2];   // producer regs: 2 j-slots live at a time

    auto ldg_half = [&](int step, int h) {
#pragma unroll
        for (int j = 0; j < 2; j++) {
            const int i = tid + (2 * h + j) * NTHREADS;   // 0..1023 float4 slots
            const int m = i >> 3, q = i & 7;
            va[j] = *reinterpret_cast<const float4*>(Ag + (long long)m * ldA + step * 32 + q * 4);
            vb[j] = *reinterpret_cast<const float4*>(Bg + (long long)m * ldB + step * 32 + q * 4);
        }
    };

    auto sts_half = [&](int s, int h) {
        uint32_t* base = smw + s * 8192;
#pragma unroll
        for (int j = 0; j < 2; j++) {
            const int i = tid + (2 * h + j) * NTHREADS;
            const int m = i >> 3, q = i & 7;
            const int kc = q >> 2;
            const int khalf = (q >> 1) & 1;
            const int tp = (q & 1) * 2;
            const float xs[4] = { va[j].x, va[j].y, va[j].z, va[j].w };
            const float ys[4] = { vb[j].x, vb[j].y, vb[j].z, vb[j].w };
            {
                const int fb = (m >> 4) * 2 + kc;
                const int reg = ((m >> 3) & 1) + 2 * khalf;
#pragma unroll
                for (int w = 0; w < 2; w++) {
                    const float x0 = xs[w * 2], x1 = xs[w * 2 + 1];
                    const uint32_t hh = bf16x2_rn(x0, x1);
                    const uint32_t ll = bf16x2_rn(x0 - bf_lo_f(hh), x1 - bf_hi_f(hh));
                    const int idx = fb * 128 + ((m & 7) * 4 + tp + w) * 4 + reg;
                    base[idx] = hh;
                    base[2048 + idx] = ll;
                }
            }
            {
                const int fb = (m >> 3) * 2 + kc;
#pragma unroll
                for (int w = 0; w < 2; w++) {
                    const float x0 = ys[w * 2], x1 = ys[w * 2 + 1];
                    const uint32_t hh = bf16x2_rn(x0, x1);
                    const uint32_t ll = bf16x2_rn(x0 - bf_lo_f(hh), x1 - bf_hi_f(hh));
                    const int idx = fb * 64 + ((m & 7) * 4 + tp + w) * 2 + khalf;
                    base[4096 + idx] = hh;
                    base[6144 + idx] = ll;
                }
            }
        }
    };

    // fragment loaders (into caller-provided register arrays)
    auto load_aF = [&](int s, int kc, uint32_t aF[2][4][4]) {
        const uint32_t* base = smw + s * 8192;
#pragma unroll
        for (int mt = 0; mt < 4; mt++) {
            const int fb = (warp_m * 4 + mt) * 2 + kc;
            const uint4 h = *reinterpret_cast<const uint4*>(base + fb * 128 + lane * 4);
            const uint4 l = *reinterpret_cast<const uint4*>(base + 2048 + fb * 128 + lane * 4);
            aF[0][mt][0] = h.x; aF[0][mt][1] = h.y; aF[0][mt][2] = h.z; aF[0][mt][3] = h.w;
            aF[1][mt][0] = l.x; aF[1][mt][1] = l.y; aF[1][mt][2] = l.z; aF[1][mt][3] = l.w;
        }
    };
    auto load_bF = [&](int s, int kc, int nh, uint32_t bF[2][2][2]) {
        const uint32_t* base = smw + s * 8192;
#pragma unroll
        for (int nt = 0; nt < 2; nt++) {
            const int fb = (warp_n * 4 + nh * 2 + nt) * 2 + kc;
            const uint2 h = *reinterpret_cast<const uint2*>(base + 4096 + fb * 64 + lane * 2);
            const uint2 l = *reinterpret_cast<const uint2*>(base + 6144 + fb * 64 + lane * 2);
            bF[0][nt][0] = h.x; bF[0][nt][1] = h.y;
            bF[1][nt][0] = l.x; bF[1][nt][1] = l.y;
        }
    };
    // 3-term MMA block for one (kc, nh): 24 MMAs into acc[.][nh*2+nt]
    auto mma_block = [&](uint32_t aF[2][4][4], uint32_t bF[2][2][2], int nh) {
#pragma unroll
        for (int mt = 0; mt < 4; mt++)
#pragma unroll
            for (int nt = 0; nt < 2; nt++)
                mma_bf16(acc[mt][nh * 2 + nt], aF[0][mt], bF[0][nt]);
#pragma unroll
        for (int mt = 0; mt < 4; mt++)
#pragma unroll
            for (int nt = 0; nt < 2; nt++)
                mma_bf16(acc[mt][nh * 2 + nt], aF[1][mt], bF[0][nt]);
#pragma unroll
        for (int mt = 0; mt < 4; mt++)
#pragma unroll
            for (int nt = 0; nt < 2; nt++)
                mma_bf16(acc[mt][nh * 2 + nt], aF[0][mt], bF[1][nt]);
    };

    const int nsteps = K / 32;
    // fill buffer 0
    ldg_half(0, 0); sts_half(0, 0);
    ldg_half(0, 1); sts_half(0, 1);
    __syncthreads();

    uint32_t aF[2][2][4][4];   // double-buffered over kc
    uint32_t bF[2][2][2][2];   // double-buffered over (kc,nh) sequence

    for (int step = 0; step < nsteps; step++) {
        const int s = step & 1;
        const bool more = (step + 1 < nsteps);

        // prologue of step: issue producer LDGs, then prefetch first fragments
        if (more) ldg_half(step + 1, 0);
        load_aF(s, 0, aF[0]);
        load_bF(s, 0, 0, bF[0]);
        load_aF(s, 1, aF[1]);      // next-kc A prefetch (independent of block 0)
        load_bF(s, 0, 1, bF[1]);   // next-nh B prefetch

        mma_block(aF[0], bF[0], 0);          // (kc0,nh0) — frags already resident
        load_bF(s, 1, 0, bF[0]);             // prefetch (kc1,nh0) over these MMAs
        if (more) { sts_half(1 - s, 0); ldg_half(step + 1, 1); }

        mma_block(aF[0], bF[1], 1);          // (kc0,nh1)
        load_bF(s, 1, 1, bF[1]);             // prefetch (kc1,nh1)

        mma_block(aF[1], bF[0], 0);          // (kc1,nh0)
        if (more) sts_half(1 - s, 1);

        mma_block(aF[1], bF[1], 1);          // (kc1,nh1)
        __syncthreads();
    }

    // epilogue: warp rows warp_m*64 .. +63, cols warp_n*32 .. +31
#pragma unroll
    for (int mt = 0; mt < 4; mt++) {
        const long long row = (long long)blockIdx.y * 128 + warp_m * 64 + mt * 16 + g;
        const long long col0 = (long long)blockIdx.x * 128 + warp_n * 32;
#pragma unroll
        for (int nt = 0; nt < 4; nt++) {
            const long long col = col0 + nt * 8 + t4 * 2;
            float2 v0 = make_float2(acc[mt][nt][0] * alpha, acc[mt][nt][1] * alpha);
            float2 v1 = make_float2(acc[mt][nt][2] * alpha, acc[mt][nt][3] * alpha);
            *reinterpret_cast<float2*>(Cg + row * ldC + col) = v0;
            *reinterpret_cast<float2*>(Cg + (row + 8) * ldC + col) = v1;
        }
    }
}

// ---------------- row softmax over S=2048 ----------------
__global__ __launch_bounds__(256) void softmax_kernel()
{
    const long long row = blockIdx.x;
    float* p = &g_scores[0] + row * (long long)S;
    const int t = threadIdx.x;

    float v[8];
    float m = -1e30f;
#pragma unroll
    for (int i = 0; i < 8; i++) {
        v[i] = p[t + i * 256];
        m = fmaxf(m, v[i]);
    }
    __shared__ float red[8];
#pragma unroll
    for (int o = 16; o; o >>= 1) m = fmaxf(m, __shfl_xor_sync(0xffffffffu, m, o));
    if ((t & 31) == 0) red[t >> 5] = m;
    __syncthreads();
    float mx = red[0];
#pragma unroll
    for (int w = 1; w < 8; w++) mx = fmaxf(mx, red[w]);

    float s = 0.f;
#pragma unroll
    for (int i = 0; i < 8; i++) {
        v[i] = __expf(v[i] - mx);
        s += v[i];
    }
#pragma unroll
    for (int o = 16; o; o >>= 1) s += __shfl_xor_sync(0xffffffffu, s, o);
    __syncthreads();
    if ((t & 31) == 0) red[t >> 5] = s;
    __syncthreads();
    float tot = 0.f;
#pragma unroll
    for (int w = 0; w < 8; w++) tot += red[w];
    const float inv = 1.0f / tot;
#pragma unroll
    for (int i = 0; i < 8; i++) p[t + i * 256] = v[i] * inv;
}

// ---------------- launch ----------------
extern "C" void kernel_launch(void* const* d_in, const int* in_sizes, int n_in,
                              void* d_out, int out_size)
{
    (void)in_sizes; (void)n_in; (void)out_size;
    const float* query = (const float*)d_in[0];
    const float* key   = (const float*)d_in[1];
    const float* value = (const float*)d_in[2];
    const float* Qw    = (const float*)d_in[3];
    const float* Kw    = (const float*)d_in[4];
    const float* Vw    = (const float*)d_in[5];
    const float* Qa    = (const float*)d_in[6];
    const float* Qb    = (const float*)d_in[7];
    const float* Ka    = (const float*)d_in[8];
    const float* Kb    = (const float*)d_in[9];
    const float* Va    = (const float*)d_in[10];
    const float* Vb    = (const float*)d_in[11];
    const float* Ow    = (const float*)d_in[12];
    float* out = (float*)d_out;

    static bool attr_done = false;
    if (!attr_done) {
        cudaFuncSetAttribute(gemm_hmma, cudaFuncAttributeMaxDynamicSharedMemorySize,
                             GEMM_SMEM_BYTES);
        attr_done = true;
    }

    const long long EE  = (long long)E * E;
    const long long BSE = (long long)BATCH * S * E;
    const long long SE  = (long long)S * E;
    const long long SS  = (long long)S * S;

    // 1. fold LoRA into weights
    weff_kernel<<<dim3(E * E / 256, 1, 3), 256>>>(Qw, Kw, Vw, Qa, Qb, Ka, Kb, Va, Vb);

    // 2. Q/K/V projections merged into ONE launch (z picks input + weight/output)
    gemm_hmma<<<dim3(E / 128, BS / 128, 3), NTHREADS, GEMM_SMEM_BYTES>>>(
        query, key, value, SEL_EXT, 0, E, 0,
        nullptr, SEL_WEFF, 0, E, EE,
        nullptr, SEL_QKV,  0, E, BSE,
        E, 1.0f);

    // 3. transpose V -> Vt[b][e][s]
    transpose_v_kernel<<<dim3(S / 32, E / 32, BATCH), 256>>>();

    // 4. scores = Q @ K^T / 32
    gemm_hmma<<<dim3(S / 128, S / 128, BATCH), NTHREADS, GEMM_SMEM_BYTES>>>(
        nullptr, nullptr, nullptr, SEL_QKV, 0, E, SE,
        nullptr, SEL_QKV,   BSE, E, SE,
        nullptr, SEL_SCORE, 0,   S, SS,
        E, 1.0f / 32.0f);

    // 5. softmax rows
    softmax_kernel<<<BATCH * S, 256>>>();

    // 6. attn_out = P @ Vt^T   (NT with Vt as [E,S] K-major)
    gemm_hmma<<<dim3(E / 128, S / 128, BATCH), NTHREADS, GEMM_SMEM_BYTES>>>(
        nullptr, nullptr, nullptr, SEL_SCORE, 0, S, SS,
        nullptr, SEL_VT,   0, S, SE,
        nullptr, SEL_AOUT, 0, E, SE,
        S, 1.0f);

    // 7. final = attn_out @ O^T
    gemm_hmma<<<dim3(E / 128, BS / 128, 1), NTHREADS, GEMM_SMEM_BYTES>>>(
        nullptr, nullptr, nullptr, SEL_AOUT, 0, E, 0,
        Ow,  SEL_EXT, 0, E, 0,
        out, SEL_EXT, 0, E, 0,
        E, 1.0f);
}